// round 4
// baseline (speedup 1.0000x reference)
#include <cuda_runtime.h>
#include <cuda_bf16.h>
#include <cstdint>
#include <cstddef>

#define Bz   4
#define Hh   8
#define LQ   1024
#define LK   1024
#define DKk  64
#define DVv  64

// ===================== helpers =====================
__device__ __forceinline__ uint32_t packbf(float lo, float hi) {
    uint32_t r;
    asm("cvt.rn.bf16x2.f32 %0, %1, %2;" : "=r"(r) : "f"(hi), "f"(lo));
    return r;
}
__device__ __forceinline__ float lo_of(float x) {
    return x - __bfloat162float(__float2bfloat16(x));
}
__device__ __forceinline__ void mma16816(float* c,
                                         uint32_t a0, uint32_t a1, uint32_t a2, uint32_t a3,
                                         uint32_t b0, uint32_t b1) {
    asm volatile(
        "mma.sync.aligned.m16n8k16.row.col.f32.bf16.bf16.f32 "
        "{%0,%1,%2,%3}, {%4,%5,%6,%7}, {%8,%9}, {%0,%1,%2,%3};"
        : "+f"(c[0]), "+f"(c[1]), "+f"(c[2]), "+f"(c[3])
        : "r"(a0), "r"(a1), "r"(a2), "r"(a3), "r"(b0), "r"(b1));
}

// smem word layout (uint32 units)
#define QTH_OFF 0          // [128j][36]  (32 kp + pad)
#define QTL_OFF 4608
#define VTH_OFF 9216       // [64n][68]   (64 jp + pad)
#define VTL_OFF 13568
#define SMEM_WORDS 17920
#define SMEM_BYTES (SMEM_WORDS * 4)

__global__ void __launch_bounds__(128, 2)
attn_kernel(const float* __restrict__ q,
            const float* __restrict__ WA,  const float* __restrict__ WB,
            const float* __restrict__ WBt, const float* __restrict__ WAt,
            const float* __restrict__ qt,  const float* __restrict__ v,
            float* __restrict__ attn, float* __restrict__ outp) {
    extern __shared__ uint32_t smw[];
    uint32_t* QTH = smw + QTH_OFF;
    uint32_t* QTL = smw + QTL_OFF;
    uint32_t* VTH = smw + VTH_OFF;
    uint32_t* VTL = smw + VTL_OFF;
    float* sf = (float*)smw;

    const int bid = blockIdx.x;
    const int mt  = bid & 15;
    const int h   = (bid >> 4) & 7;
    const int b   = bid >> 7;
    const int i0  = mt * 64;

    const int t    = threadIdx.x;
    const int w    = t >> 5;
    const int lane = t & 31;
    const int grp  = lane >> 2;
    const int q4   = lane & 3;

    const float* qtp = qt + ((size_t)(b * Hh + h) * DKk) * LK;   // [64][1024]
    const float* vp  = v  + ((size_t)(b * Hh + h) * LK) * DVv;   // [1024][64]
    float* attn_base = attn + ((size_t)(b * Hh + h) * LQ + i0) * (size_t)LK;
    float* out_base  = outp + ((size_t)(b * Hh + h) * LQ + i0) * (size_t)DVv;

    // ======== fused prologue: Wc chain + P = q@Wc + A-fragments ========
    // overlays: sA(2048)@0 sB(512)@2048 sBt(512)@2560 sAt(2048)@3072
    //           sT1(1024)@5120 sT2(2048)@6144 ; sWc(4096)@9216 ; sP(64x68)@13568
    {
        float* sA  = sf;
        float* sB  = sf + 2048;
        float* sBt = sf + 2560;
        float* sAt = sf + 3072;
        float* sT1 = sf + 5120;
        float* sT2 = sf + 6144;
        float* sWc = sf + 9216;

        for (int i = t; i < 2048; i += 128) sA[i]  = WA [h * 2048 + i];
        for (int i = t; i < 512;  i += 128) sB[i]  = WB [h * 512  + i];
        for (int i = t; i < 512;  i += 128) sBt[i] = WBt[h * 512  + i];
        for (int i = t; i < 2048; i += 128) sAt[i] = WAt[h * 2048 + i];
        __syncthreads();

        for (int i = t; i < 1024; i += 128) {           // T1[64][16]
            int r = i >> 4, c = i & 15;
            float s = 0.f;
            #pragma unroll
            for (int k = 0; k < 32; k++) s += sA[r * 32 + k] * sB[k * 16 + c];
            sT1[i] = s;
        }
        __syncthreads();
        for (int i = t; i < 2048; i += 128) {           // T2[64][32]
            int r = i >> 5, c = i & 31;
            float s = 0.f;
            #pragma unroll
            for (int k = 0; k < 16; k++) s += sT1[r * 16 + k] * sBt[k * 32 + c];
            sT2[i] = s;
        }
        __syncthreads();
        for (int i = t; i < 4096; i += 128) {           // Wc[64k][64d] * 1/8
            int r = i >> 6, c = i & 63;
            float s = 0.f;
            #pragma unroll
            for (int k = 0; k < 32; k++) s += sT2[r * 32 + k] * sAt[k * 64 + c];
            sWc[i] = s * 0.125f;
        }
        __syncthreads();

        // load q rows -> sQ (reuse sf+0, pitch 65)
        float* sQ = sf;
        for (int i = t; i < 4096; i += 128) {
            int r = i >> 6, k = i & 63;
            sQ[r * 65 + k] = q[((size_t)(b * LQ + i0 + r) * Hh + h) * DKk + k];
        }
        __syncthreads();

        // P[64][64] -> sP (pitch 68)
        float* sP = sf + 13568;
        {
            const int c  = t & 63;
            const int rh = t >> 6;                       // 0..1
            #pragma unroll 1
            for (int j = 0; j < 32; j++) {
                int r = rh + 2 * j;
                float s = 0.f;
                #pragma unroll
                for (int k = 0; k < 64; k++) s += sQ[r * 65 + k] * sWc[k * 64 + c];
                sP[r * 68 + c] = s;
            }
        }
        __syncthreads();
    }

    // ---- persistent A fragments of P (hi/lo), warp rows w*16 .. +15 ----
    const int rA = w * 16 + grp;
    const int rB = rA + 8;
    uint32_t pah[4][4], pal[4][4];
    {
        const float* sP = sf + 13568;
        #pragma unroll
        for (int kt = 0; kt < 4; kt++) {
            int k = kt * 16 + 2 * q4;
            float x0 = sP[rA * 68 + k],     x1 = sP[rA * 68 + k + 1];
            float y0 = sP[rB * 68 + k],     y1 = sP[rB * 68 + k + 1];
            float x8 = sP[rA * 68 + k + 8], x9 = sP[rA * 68 + k + 9];
            float y8 = sP[rB * 68 + k + 8], y9 = sP[rB * 68 + k + 9];
            pah[kt][0] = packbf(x0, x1); pah[kt][1] = packbf(y0, y1);
            pah[kt][2] = packbf(x8, x9); pah[kt][3] = packbf(y8, y9);
            pal[kt][0] = packbf(lo_of(x0), lo_of(x1));
            pal[kt][1] = packbf(lo_of(y0), lo_of(y1));
            pal[kt][2] = packbf(lo_of(x8), lo_of(x9));
            pal[kt][3] = packbf(lo_of(y8), lo_of(y9));
        }
    }
    __syncthreads();

    float m0 = -1e30f, m1 = -1e30f, s0 = 0.f, s1 = 0.f;

    // ================= PASS A: online (max,sum), hi-only MMA =================
    #pragma unroll 1
    for (int ch = 0; ch < 8; ch++) {
        const int j0 = ch * 128;
        __syncthreads();
        #pragma unroll 1
        for (int i = 0; i < 32; i++) {
            int idx = t + 128 * i;
            int j = idx & 127, kp = idx >> 7;
            float f0 = qtp[(size_t)(2 * kp) * LK + j0 + j];
            float f1 = qtp[(size_t)(2 * kp + 1) * LK + j0 + j];
            QTH[j * 36 + kp] = packbf(f0, f1);
        }
        __syncthreads();

        #pragma unroll
        for (int h2 = 0; h2 < 2; h2++) {
            float acc[8][4];
            #pragma unroll
            for (int nt = 0; nt < 8; nt++) {
                #pragma unroll
                for (int u = 0; u < 4; u++) acc[nt][u] = 0.f;
                const uint32_t* Brow = QTH + (8 * (h2 * 8 + nt) + grp) * 36 + q4;
                #pragma unroll
                for (int kt = 0; kt < 4; kt++)
                    mma16816(acc[nt], pah[kt][0], pah[kt][1], pah[kt][2], pah[kt][3],
                             Brow[8 * kt], Brow[8 * kt + 4]);
            }
            float cm0 = -1e30f, cm1 = -1e30f;
            #pragma unroll
            for (int nt = 0; nt < 8; nt++) {
                cm0 = fmaxf(cm0, fmaxf(acc[nt][0], acc[nt][1]));
                cm1 = fmaxf(cm1, fmaxf(acc[nt][2], acc[nt][3]));
            }
            cm0 = fmaxf(cm0, __shfl_xor_sync(0xffffffffu, cm0, 1));
            cm0 = fmaxf(cm0, __shfl_xor_sync(0xffffffffu, cm0, 2));
            cm1 = fmaxf(cm1, __shfl_xor_sync(0xffffffffu, cm1, 1));
            cm1 = fmaxf(cm1, __shfl_xor_sync(0xffffffffu, cm1, 2));
            float nm0 = fmaxf(m0, cm0), nm1 = fmaxf(m1, cm1);
            float sn0 = 0.f, sn1 = 0.f;
            #pragma unroll
            for (int nt = 0; nt < 8; nt++) {
                sn0 += __expf(acc[nt][0] - nm0) + __expf(acc[nt][1] - nm0);
                sn1 += __expf(acc[nt][2] - nm1) + __expf(acc[nt][3] - nm1);
            }
            sn0 += __shfl_xor_sync(0xffffffffu, sn0, 1);
            sn0 += __shfl_xor_sync(0xffffffffu, sn0, 2);
            sn1 += __shfl_xor_sync(0xffffffffu, sn1, 1);
            sn1 += __shfl_xor_sync(0xffffffffu, sn1, 2);
            s0 = s0 * __expf(m0 - nm0) + sn0;  m0 = nm0;
            s1 = s1 * __expf(m1 - nm1) + sn1;  m1 = nm1;
        }
    }
    const float is0 = 1.f / s0;
    const float is1 = 1.f / s1;

    // ================= PASS B: 3-term S, attn out, O += E@V =================
    float oacc[8][4];
    #pragma unroll
    for (int nt = 0; nt < 8; nt++)
        #pragma unroll
        for (int u = 0; u < 4; u++) oacc[nt][u] = 0.f;

    #pragma unroll 1
    for (int ch = 0; ch < 8; ch++) {
        const int j0 = ch * 128;
        __syncthreads();
        #pragma unroll 1
        for (int i = 0; i < 32; i++) {      // qtT hi+lo
            int idx = t + 128 * i;
            int j = idx & 127, kp = idx >> 7;
            float f0 = qtp[(size_t)(2 * kp) * LK + j0 + j];
            float f1 = qtp[(size_t)(2 * kp + 1) * LK + j0 + j];
            QTH[j * 36 + kp] = packbf(f0, f1);
            QTL[j * 36 + kp] = packbf(lo_of(f0), lo_of(f1));
        }
        #pragma unroll 1
        for (int i = 0; i < 32; i++) {      // VT hi+lo
            int idx = t + 128 * i;
            int n = idx & 63, jp = idx >> 6;
            float f0 = vp[(size_t)(j0 + 2 * jp) * DVv + n];
            float f1 = vp[(size_t)(j0 + 2 * jp + 1) * DVv + n];
            VTH[n * 68 + jp] = packbf(f0, f1);
            VTL[n * 68 + jp] = packbf(lo_of(f0), lo_of(f1));
        }
        __syncthreads();

        #pragma unroll
        for (int h2 = 0; h2 < 2; h2++) {
            float acc[8][4];
            #pragma unroll
            for (int nt = 0; nt < 8; nt++) {
                #pragma unroll
                for (int u = 0; u < 4; u++) acc[nt][u] = 0.f;
                const uint32_t* Bh = QTH + (8 * (h2 * 8 + nt) + grp) * 36 + q4;
                const uint32_t* Bl = QTL + (8 * (h2 * 8 + nt) + grp) * 36 + q4;
                #pragma unroll
                for (int kt = 0; kt < 4; kt++) {
                    uint32_t bh0 = Bh[8 * kt], bh1 = Bh[8 * kt + 4];
                    uint32_t bl0 = Bl[8 * kt], bl1 = Bl[8 * kt + 4];
                    mma16816(acc[nt], pah[kt][0], pah[kt][1], pah[kt][2], pah[kt][3], bh0, bh1);
                    mma16816(acc[nt], pah[kt][0], pah[kt][1], pah[kt][2], pah[kt][3], bl0, bl1);
                    mma16816(acc[nt], pal[kt][0], pal[kt][1], pal[kt][2], pal[kt][3], bh0, bh1);
                }
            }

            #pragma unroll
            for (int kt2 = 0; kt2 < 4; kt2++) {
                const int t0 = 2 * kt2, t1 = 2 * kt2 + 1;
                float e00 = __expf(acc[t0][0] - m0) * is0;
                float e01 = __expf(acc[t0][1] - m0) * is0;
                float e02 = __expf(acc[t0][2] - m1) * is1;
                float e03 = __expf(acc[t0][3] - m1) * is1;
                float e10 = __expf(acc[t1][0] - m0) * is0;
                float e11 = __expf(acc[t1][1] - m0) * is0;
                float e12 = __expf(acc[t1][2] - m1) * is1;
                float e13 = __expf(acc[t1][3] - m1) * is1;

                const int cb = j0 + h2 * 64 + 16 * kt2 + 2 * q4;
                *(float2*)&attn_base[(size_t)rA * LK + cb]     = make_float2(e00, e01);
                *(float2*)&attn_base[(size_t)rB * LK + cb]     = make_float2(e02, e03);
                *(float2*)&attn_base[(size_t)rA * LK + cb + 8] = make_float2(e10, e11);
                *(float2*)&attn_base[(size_t)rB * LK + cb + 8] = make_float2(e12, e13);

                uint32_t eh0 = packbf(e00, e01), eh1 = packbf(e02, e03);
                uint32_t eh2 = packbf(e10, e11), eh3 = packbf(e12, e13);
                uint32_t el0 = packbf(lo_of(e00), lo_of(e01));
                uint32_t el1 = packbf(lo_of(e02), lo_of(e03));
                uint32_t el2 = packbf(lo_of(e10), lo_of(e11));
                uint32_t el3 = packbf(lo_of(e12), lo_of(e13));

                const int jpb = 32 * h2 + 8 * kt2 + q4;
                #pragma unroll
                for (int nt = 0; nt < 8; nt++) {
                    const uint32_t* Vh = VTH + (8 * nt + grp) * 68 + jpb;
                    const uint32_t* Vl = VTL + (8 * nt + grp) * 68 + jpb;
                    uint32_t vh0 = Vh[0], vh1 = Vh[4];
                    uint32_t vl0 = Vl[0], vl1 = Vl[4];
                    mma16816(oacc[nt], eh0, eh1, eh2, eh3, vh0, vh1);
                    mma16816(oacc[nt], eh0, eh1, eh2, eh3, vl0, vl1);
                    mma16816(oacc[nt], el0, el1, el2, el3, vh0, vh1);
                }
            }
        }
    }

    // ================= epilogue: O store =================
    #pragma unroll
    for (int nt = 0; nt < 8; nt++) {
        *(float2*)&out_base[(size_t)rA * DVv + 8 * nt + 2 * q4] =
            make_float2(oacc[nt][0], oacc[nt][1]);
        *(float2*)&out_base[(size_t)rB * DVv + 8 * nt + 2 * q4] =
            make_float2(oacc[nt][2], oacc[nt][3]);
    }
}

// ===================== launch =====================
extern "C" void kernel_launch(void* const* d_in, const int* in_sizes, int n_in,
                              void* d_out, int out_size) {
    const float* q   = (const float*)d_in[0];
    const float* WA  = (const float*)d_in[1];
    const float* WB  = (const float*)d_in[2];
    const float* WAt = (const float*)d_in[3];
    const float* WBt = (const float*)d_in[4];
    const float* qt  = (const float*)d_in[5];
    const float* v   = (const float*)d_in[6];

    float* outp = (float*)d_out;
    const size_t attn_elems = (size_t)Bz * Hh * LQ * LK;
    float* attn = outp + ((size_t)out_size - attn_elems);

    cudaFuncSetAttribute(attn_kernel, cudaFuncAttributeMaxDynamicSharedMemorySize,
                         SMEM_BYTES);

    attn_kernel<<<Bz * Hh * 16, 128, SMEM_BYTES>>>(q, WA, WB, WBt, WAt, qt, v, attn, outp);
}

// round 5
// speedup vs baseline: 3.6195x; 3.6195x over previous
#include <cuda_runtime.h>
#include <cuda_bf16.h>
#include <cstdint>
#include <cstddef>

#define Bz   4
#define Hh   8
#define LQ   1024
#define LK   1024
#define DKk  64
#define DVv  64

// ===================== helpers =====================
__device__ __forceinline__ uint32_t packbf(float lo, float hi) {
    uint32_t r;
    asm("cvt.rn.bf16x2.f32 %0, %1, %2;" : "=r"(r) : "f"(hi), "f"(lo));
    return r;
}
__device__ __forceinline__ float lo_of(float x) {
    return x - __bfloat162float(__float2bfloat16(x));
}
__device__ __forceinline__ void mma16816(float* c,
                                         uint32_t a0, uint32_t a1, uint32_t a2, uint32_t a3,
                                         uint32_t b0, uint32_t b1) {
    asm volatile(
        "mma.sync.aligned.m16n8k16.row.col.f32.bf16.bf16.f32 "
        "{%0,%1,%2,%3}, {%4,%5,%6,%7}, {%8,%9}, {%0,%1,%2,%3};"
        : "+f"(c[0]), "+f"(c[1]), "+f"(c[2]), "+f"(c[3])
        : "r"(a0), "r"(a1), "r"(a2), "r"(a3), "r"(b0), "r"(b1));
}

// smem word layout (uint32 units)
#define QTH_OFF 0          // [128j][36]
#define QTL_OFF 4608
#define VTH_OFF 9216       // [64n][68]
#define VTL_OFF 13568
#define SMEM_WORDS 17920
#define SMEM_BYTES (SMEM_WORDS * 4)
// prologue overlays (words): sA@0(2048) sB@2048(512) sBt@2560(512) sAt@3072(2048)
//                            sT1@5120(1024) sT2@6144(2048) sWc@8192(4096)

__global__ void __launch_bounds__(256, 2)
attn_kernel(const float* __restrict__ q,
            const float* __restrict__ WA,  const float* __restrict__ WB,
            const float* __restrict__ WBt, const float* __restrict__ WAt,
            const float* __restrict__ qt,  const float* __restrict__ v,
            float* __restrict__ attn, float* __restrict__ outp) {
    extern __shared__ uint32_t smw[];
    uint32_t* QTH = smw + QTH_OFF;
    uint32_t* QTL = smw + QTL_OFF;
    uint32_t* VTH = smw + VTH_OFF;
    uint32_t* VTL = smw + VTL_OFF;
    float* sf = (float*)smw;

    const int bid = blockIdx.x;
    const int mt  = bid & 7;
    const int h   = (bid >> 3) & 7;
    const int b   = bid >> 6;
    const int i0  = mt * 128;

    const int t    = threadIdx.x;
    const int w    = t >> 5;
    const int lane = t & 31;
    const int grp  = lane >> 2;
    const int q4   = lane & 3;

    const float* qtp = qt + ((size_t)(b * Hh + h) * DKk) * LK;   // [64][1024]
    const float* vp  = v  + ((size_t)(b * Hh + h) * LK) * DVv;   // [1024][64]
    float* attn_base = attn + ((size_t)(b * Hh + h) * LQ + i0) * (size_t)LK;
    float* out_base  = outp + ((size_t)(b * Hh + h) * LQ + i0) * (size_t)DVv;

    const int rA = w * 16 + grp;
    const int rB = rA + 8;

    // ======== prologue 1: Wc = (A@B@Bt@At)/8 into smem ========
    {
        float* sA  = sf;
        float* sB  = sf + 2048;
        float* sBt = sf + 2560;
        float* sAt = sf + 3072;
        float* sT1 = sf + 5120;
        float* sT2 = sf + 6144;
        float* sWc = sf + 8192;

        for (int i = t; i < 2048; i += 256) sA[i]  = WA [h * 2048 + i];
        for (int i = t; i < 512;  i += 256) sB[i]  = WB [h * 512  + i];
        for (int i = t; i < 512;  i += 256) sBt[i] = WBt[h * 512  + i];
        for (int i = t; i < 2048; i += 256) sAt[i] = WAt[h * 2048 + i];
        __syncthreads();

        #pragma unroll
        for (int i = t; i < 1024; i += 256) {           // T1[64][16]
            int r = i >> 4, c = i & 15;
            float s = 0.f;
            #pragma unroll
            for (int k = 0; k < 32; k++) s += sA[r * 32 + k] * sB[k * 16 + c];
            sT1[i] = s;
        }
        __syncthreads();
        #pragma unroll
        for (int i = t; i < 2048; i += 256) {           // T2[64][32]
            int r = i >> 5, c = i & 31;
            float s = 0.f;
            #pragma unroll
            for (int k = 0; k < 16; k++) s += sT1[r * 16 + k] * sBt[k * 32 + c];
            sT2[i] = s;
        }
        __syncthreads();
        #pragma unroll
        for (int i = t; i < 4096; i += 256) {           // Wc[64k][64d] * 1/8
            int r = i >> 6, c = i & 63;
            float s = 0.f;
            #pragma unroll
            for (int k = 0; k < 32; k++) s += sT2[r * 32 + k] * sAt[k * 64 + c];
            sWc[i] = s * 0.125f;
        }
        __syncthreads();
    }

    // ======== prologue 2: P fragments via MMA (P = Q @ Wc, 3-term) ========
    uint32_t pah[4][4], pal[4][4];
    {
        const float* sWc = sf + 8192;
        // Q A-fragments (hi/lo) straight from gmem
        uint32_t qah[4][4], qal[4][4];
        const float* qr0 = q + ((size_t)(b * LQ + i0 + rA) * Hh + h) * DKk;
        const float* qr1 = q + ((size_t)(b * LQ + i0 + rB) * Hh + h) * DKk;
        #pragma unroll
        for (int kt = 0; kt < 4; kt++) {
            int k = 16 * kt + 2 * q4;
            float2 x0 = *(const float2*)&qr0[k];
            float2 x8 = *(const float2*)&qr0[k + 8];
            float2 y0 = *(const float2*)&qr1[k];
            float2 y8 = *(const float2*)&qr1[k + 8];
            qah[kt][0] = packbf(x0.x, x0.y); qah[kt][1] = packbf(y0.x, y0.y);
            qah[kt][2] = packbf(x8.x, x8.y); qah[kt][3] = packbf(y8.x, y8.y);
            qal[kt][0] = packbf(lo_of(x0.x), lo_of(x0.y));
            qal[kt][1] = packbf(lo_of(y0.x), lo_of(y0.y));
            qal[kt][2] = packbf(lo_of(x8.x), lo_of(x8.y));
            qal[kt][3] = packbf(lo_of(y8.x), lo_of(y8.y));
        }
        #pragma unroll
        for (int kt2 = 0; kt2 < 4; kt2++) {
            float p0[4] = {0.f, 0.f, 0.f, 0.f};
            float p1[4] = {0.f, 0.f, 0.f, 0.f};
            #pragma unroll
            for (int nt2 = 0; nt2 < 2; nt2++) {
                float* pc = nt2 ? p1 : p0;
                const int ncol = 8 * (2 * kt2 + nt2) + grp;
                #pragma unroll
                for (int kq = 0; kq < 4; kq++) {
                    int kk = 16 * kq + 2 * q4;
                    float w0 = sWc[kk * 64 + ncol];
                    float w1 = sWc[(kk + 1) * 64 + ncol];
                    float w8 = sWc[(kk + 8) * 64 + ncol];
                    float w9 = sWc[(kk + 9) * 64 + ncol];
                    uint32_t bh0 = packbf(w0, w1), bh1 = packbf(w8, w9);
                    uint32_t bl0 = packbf(lo_of(w0), lo_of(w1));
                    uint32_t bl1 = packbf(lo_of(w8), lo_of(w9));
                    mma16816(pc, qah[kq][0], qah[kq][1], qah[kq][2], qah[kq][3], bh0, bh1);
                    mma16816(pc, qah[kq][0], qah[kq][1], qah[kq][2], qah[kq][3], bl0, bl1);
                    mma16816(pc, qal[kq][0], qal[kq][1], qal[kq][2], qal[kq][3], bh0, bh1);
                }
            }
            pah[kt2][0] = packbf(p0[0], p0[1]); pah[kt2][1] = packbf(p0[2], p0[3]);
            pah[kt2][2] = packbf(p1[0], p1[1]); pah[kt2][3] = packbf(p1[2], p1[3]);
            pal[kt2][0] = packbf(lo_of(p0[0]), lo_of(p0[1]));
            pal[kt2][1] = packbf(lo_of(p0[2]), lo_of(p0[3]));
            pal[kt2][2] = packbf(lo_of(p1[0]), lo_of(p1[1]));
            pal[kt2][3] = packbf(lo_of(p1[2]), lo_of(p1[3]));
        }
    }

    float m0 = -1e30f, m1 = -1e30f, s0 = 0.f, s1 = 0.f;

    // ================= PASS A: online (max,sum), hi-only MMA =================
    #pragma unroll 1
    for (int ch = 0; ch < 8; ch++) {
        const int j0 = ch * 128;
        __syncthreads();
        #pragma unroll
        for (int it = 0; it < 4; it++) {           // qtT hi (batched float4 loads)
            int idx = t + 256 * it;
            int kp = idx >> 5;
            int jg = (idx & 31) << 2;
            float4 a = *(const float4*)&qtp[(size_t)(2 * kp) * LK + j0 + jg];
            float4 c = *(const float4*)&qtp[(size_t)(2 * kp + 1) * LK + j0 + jg];
            QTH[(jg + 0) * 36 + kp] = packbf(a.x, c.x);
            QTH[(jg + 1) * 36 + kp] = packbf(a.y, c.y);
            QTH[(jg + 2) * 36 + kp] = packbf(a.z, c.z);
            QTH[(jg + 3) * 36 + kp] = packbf(a.w, c.w);
        }
        __syncthreads();

        #pragma unroll
        for (int h2 = 0; h2 < 2; h2++) {
            float acc[8][4];
            #pragma unroll
            for (int nt = 0; nt < 8; nt++) {
                #pragma unroll
                for (int u = 0; u < 4; u++) acc[nt][u] = 0.f;
                const uint32_t* Brow = QTH + (8 * (h2 * 8 + nt) + grp) * 36 + q4;
                #pragma unroll
                for (int kt = 0; kt < 4; kt++)
                    mma16816(acc[nt], pah[kt][0], pah[kt][1], pah[kt][2], pah[kt][3],
                             Brow[8 * kt], Brow[8 * kt + 4]);
            }
            float cm0 = -1e30f, cm1 = -1e30f;
            #pragma unroll
            for (int nt = 0; nt < 8; nt++) {
                cm0 = fmaxf(cm0, fmaxf(acc[nt][0], acc[nt][1]));
                cm1 = fmaxf(cm1, fmaxf(acc[nt][2], acc[nt][3]));
            }
            cm0 = fmaxf(cm0, __shfl_xor_sync(0xffffffffu, cm0, 1));
            cm0 = fmaxf(cm0, __shfl_xor_sync(0xffffffffu, cm0, 2));
            cm1 = fmaxf(cm1, __shfl_xor_sync(0xffffffffu, cm1, 1));
            cm1 = fmaxf(cm1, __shfl_xor_sync(0xffffffffu, cm1, 2));
            float nm0 = fmaxf(m0, cm0), nm1 = fmaxf(m1, cm1);
            float sn0 = 0.f, sn1 = 0.f;
            #pragma unroll
            for (int nt = 0; nt < 8; nt++) {
                sn0 += __expf(acc[nt][0] - nm0) + __expf(acc[nt][1] - nm0);
                sn1 += __expf(acc[nt][2] - nm1) + __expf(acc[nt][3] - nm1);
            }
            sn0 += __shfl_xor_sync(0xffffffffu, sn0, 1);
            sn0 += __shfl_xor_sync(0xffffffffu, sn0, 2);
            sn1 += __shfl_xor_sync(0xffffffffu, sn1, 1);
            sn1 += __shfl_xor_sync(0xffffffffu, sn1, 2);
            s0 = s0 * __expf(m0 - nm0) + sn0;  m0 = nm0;
            s1 = s1 * __expf(m1 - nm1) + sn1;  m1 = nm1;
        }
    }
    const float is0 = 1.f / s0;
    const float is1 = 1.f / s1;

    // ================= PASS B: 3-term S, attn out, O += E@V =================
    float oacc[8][4];
    #pragma unroll
    for (int nt = 0; nt < 8; nt++)
        #pragma unroll
        for (int u = 0; u < 4; u++) oacc[nt][u] = 0.f;

    #pragma unroll 1
    for (int ch = 0; ch < 8; ch++) {
        const int j0 = ch * 128;
        __syncthreads();
        #pragma unroll
        for (int it = 0; it < 4; it++) {           // qtT hi+lo
            int idx = t + 256 * it;
            int kp = idx >> 5;
            int jg = (idx & 31) << 2;
            float4 a = *(const float4*)&qtp[(size_t)(2 * kp) * LK + j0 + jg];
            float4 c = *(const float4*)&qtp[(size_t)(2 * kp + 1) * LK + j0 + jg];
            QTH[(jg + 0) * 36 + kp] = packbf(a.x, c.x);
            QTH[(jg + 1) * 36 + kp] = packbf(a.y, c.y);
            QTH[(jg + 2) * 36 + kp] = packbf(a.z, c.z);
            QTH[(jg + 3) * 36 + kp] = packbf(a.w, c.w);
            QTL[(jg + 0) * 36 + kp] = packbf(lo_of(a.x), lo_of(c.x));
            QTL[(jg + 1) * 36 + kp] = packbf(lo_of(a.y), lo_of(c.y));
            QTL[(jg + 2) * 36 + kp] = packbf(lo_of(a.z), lo_of(c.z));
            QTL[(jg + 3) * 36 + kp] = packbf(lo_of(a.w), lo_of(c.w));
        }
        #pragma unroll
        for (int it = 0; it < 4; it++) {           // VT hi+lo
            int idx = t + 256 * it;
            int jp = idx >> 4;
            int ng = (idx & 15) << 2;
            float4 a = *(const float4*)&vp[(size_t)(j0 + 2 * jp) * DVv + ng];
            float4 c = *(const float4*)&vp[(size_t)(j0 + 2 * jp + 1) * DVv + ng];
            VTH[(ng + 0) * 68 + jp] = packbf(a.x, c.x);
            VTH[(ng + 1) * 68 + jp] = packbf(a.y, c.y);
            VTH[(ng + 2) * 68 + jp] = packbf(a.z, c.z);
            VTH[(ng + 3) * 68 + jp] = packbf(a.w, c.w);
            VTL[(ng + 0) * 68 + jp] = packbf(lo_of(a.x), lo_of(c.x));
            VTL[(ng + 1) * 68 + jp] = packbf(lo_of(a.y), lo_of(c.y));
            VTL[(ng + 2) * 68 + jp] = packbf(lo_of(a.z), lo_of(c.z));
            VTL[(ng + 3) * 68 + jp] = packbf(lo_of(a.w), lo_of(c.w));
        }
        __syncthreads();

        #pragma unroll
        for (int h2 = 0; h2 < 2; h2++) {
            float acc[8][4];
            #pragma unroll
            for (int nt = 0; nt < 8; nt++) {
                #pragma unroll
                for (int u = 0; u < 4; u++) acc[nt][u] = 0.f;
                const uint32_t* Bh = QTH + (8 * (h2 * 8 + nt) + grp) * 36 + q4;
                const uint32_t* Bl = QTL + (8 * (h2 * 8 + nt) + grp) * 36 + q4;
                #pragma unroll
                for (int kt = 0; kt < 4; kt++) {
                    uint32_t bh0 = Bh[8 * kt], bh1 = Bh[8 * kt + 4];
                    uint32_t bl0 = Bl[8 * kt], bl1 = Bl[8 * kt + 4];
                    mma16816(acc[nt], pah[kt][0], pah[kt][1], pah[kt][2], pah[kt][3], bh0, bh1);
                    mma16816(acc[nt], pah[kt][0], pah[kt][1], pah[kt][2], pah[kt][3], bl0, bl1);
                    mma16816(acc[nt], pal[kt][0], pal[kt][1], pal[kt][2], pal[kt][3], bh0, bh1);
                }
            }

            #pragma unroll
            for (int kt2 = 0; kt2 < 4; kt2++) {
                const int t0 = 2 * kt2, t1 = 2 * kt2 + 1;
                float e00 = __expf(acc[t0][0] - m0) * is0;
                float e01 = __expf(acc[t0][1] - m0) * is0;
                float e02 = __expf(acc[t0][2] - m1) * is1;
                float e03 = __expf(acc[t0][3] - m1) * is1;
                float e10 = __expf(acc[t1][0] - m0) * is0;
                float e11 = __expf(acc[t1][1] - m0) * is0;
                float e12 = __expf(acc[t1][2] - m1) * is1;
                float e13 = __expf(acc[t1][3] - m1) * is1;

                const int cb = j0 + h2 * 64 + 16 * kt2 + 2 * q4;
                *(float2*)&attn_base[(size_t)rA * LK + cb]     = make_float2(e00, e01);
                *(float2*)&attn_base[(size_t)rB * LK + cb]     = make_float2(e02, e03);
                *(float2*)&attn_base[(size_t)rA * LK + cb + 8] = make_float2(e10, e11);
                *(float2*)&attn_base[(size_t)rB * LK + cb + 8] = make_float2(e12, e13);

                uint32_t eh0 = packbf(e00, e01), eh1 = packbf(e02, e03);
                uint32_t eh2 = packbf(e10, e11), eh3 = packbf(e12, e13);
                uint32_t el0 = packbf(lo_of(e00), lo_of(e01));
                uint32_t el1 = packbf(lo_of(e02), lo_of(e03));
                uint32_t el2 = packbf(lo_of(e10), lo_of(e11));
                uint32_t el3 = packbf(lo_of(e12), lo_of(e13));

                const int jpb = 32 * h2 + 8 * kt2 + q4;
                #pragma unroll
                for (int nt = 0; nt < 8; nt++) {
                    const uint32_t* Vh = VTH + (8 * nt + grp) * 68 + jpb;
                    const uint32_t* Vl = VTL + (8 * nt + grp) * 68 + jpb;
                    uint32_t vh0 = Vh[0], vh1 = Vh[4];
                    uint32_t vl0 = Vl[0], vl1 = Vl[4];
                    mma16816(oacc[nt], eh0, eh1, eh2, eh3, vh0, vh1);
                    mma16816(oacc[nt], eh0, eh1, eh2, eh3, vl0, vl1);
                    mma16816(oacc[nt], el0, el1, el2, el3, vh0, vh1);
                }
            }
        }
    }

    // ================= epilogue: O store =================
    #pragma unroll
    for (int nt = 0; nt < 8; nt++) {
        *(float2*)&out_base[(size_t)rA * DVv + 8 * nt + 2 * q4] =
            make_float2(oacc[nt][0], oacc[nt][1]);
        *(float2*)&out_base[(size_t)rB * DVv + 8 * nt + 2 * q4] =
            make_float2(oacc[nt][2], oacc[nt][3]);
    }
}

// ===================== launch =====================
extern "C" void kernel_launch(void* const* d_in, const int* in_sizes, int n_in,
                              void* d_out, int out_size) {
    const float* q   = (const float*)d_in[0];
    const float* WA  = (const float*)d_in[1];
    const float* WB  = (const float*)d_in[2];
    const float* WAt = (const float*)d_in[3];
    const float* WBt = (const float*)d_in[4];
    const float* qt  = (const float*)d_in[5];
    const float* v   = (const float*)d_in[6];

    float* outp = (float*)d_out;
    const size_t attn_elems = (size_t)Bz * Hh * LQ * LK;
    float* attn = outp + ((size_t)out_size - attn_elems);

    cudaFuncSetAttribute(attn_kernel, cudaFuncAttributeMaxDynamicSharedMemorySize,
                         SMEM_BYTES);

    attn_kernel<<<Bz * Hh * 8, 256, SMEM_BYTES>>>(q, WA, WB, WBt, WAt, qt, v, attn, outp);
}